// round 2
// baseline (speedup 1.0000x reference)
#include <cuda_runtime.h>
#include <cuda_bf16.h>
#include <math.h>

#define BATCH 96
#define N1 196
#define N2 77
#define DIM 512
#define KT 16

// scratch logits (no cudaMalloc allowed)
__device__ float g_i2t[BATCH * BATCH];
__device__ float g_t2i[BATCH * BATCH];

// Block (b,c): compute S[q,r] = img[b,q] . txt[c,r] for q<196, r<77.
//   i2t[b,c] = mean_q max_r S
//   t2i[c,b] = mean_r max_q S
// 256 threads = (tx in [0,16) over r, ty in [0,16) over q).
// Per-thread register tile: 13 q-rows (q=ty+16i), 5 r-cols (r=tx+16j).
__global__ __launch_bounds__(256, 2)
void sim_kernel(const float* __restrict__ img_all, const float* __restrict__ txt_all) {
    const int b = blockIdx.x;
    const int c = blockIdx.y;
    const float* __restrict__ img = img_all + (size_t)b * N1 * DIM;
    const float* __restrict__ txt = txt_all + (size_t)c * N2 * DIM;

    // padded shared tiles: [kk][elem]; 209/81 padding keeps stores conflict-light
    __shared__ float sImg[KT][209];   // cols 196..208 are zero pad
    __shared__ float sTxt[KT][81];    // cols 77..80 are zero pad
    __shared__ float colPart[16][80];
    __shared__ float rowRes[N1];
    __shared__ float wrSum[8];
    __shared__ float wcSum[8];

    const int tid = threadIdx.x;
    const int tx = tid & 15;          // r group
    const int ty = tid >> 4;          // q group

    // zero the pad columns once (never overwritten by tile loads)
    for (int idx = tid; idx < KT * 13; idx += 256) {
        sImg[idx / 13][196 + (idx % 13)] = 0.0f;
    }
    for (int idx = tid; idx < KT * 4; idx += 256) {
        sTxt[idx / 4][77 + (idx % 4)] = 0.0f;
    }

    float acc[13][5];
    #pragma unroll
    for (int i = 0; i < 13; i++)
        #pragma unroll
        for (int j = 0; j < 5; j++)
            acc[i][j] = 0.0f;

    for (int k0 = 0; k0 < DIM; k0 += KT) {
        __syncthreads();   // protect previous-iteration reads (and pad init on iter 0)
        // load img chunk: 196 rows x 16 k (float4 per thread-item)
        for (int idx = tid; idx < N1 * 4; idx += 256) {
            int q = idx >> 2, seg = idx & 3;
            float4 v = *(const float4*)(img + (size_t)q * DIM + k0 + seg * 4);
            sImg[seg * 4 + 0][q] = v.x;
            sImg[seg * 4 + 1][q] = v.y;
            sImg[seg * 4 + 2][q] = v.z;
            sImg[seg * 4 + 3][q] = v.w;
        }
        // load txt chunk: 77 rows x 16 k
        for (int idx = tid; idx < N2 * 4; idx += 256) {
            int r = idx >> 2, seg = idx & 3;
            float4 v = *(const float4*)(txt + (size_t)r * DIM + k0 + seg * 4);
            sTxt[seg * 4 + 0][r] = v.x;
            sTxt[seg * 4 + 1][r] = v.y;
            sTxt[seg * 4 + 2][r] = v.z;
            sTxt[seg * 4 + 3][r] = v.w;
        }
        __syncthreads();

        #pragma unroll
        for (int kk = 0; kk < KT; kk++) {
            float a[13], bb[5];
            #pragma unroll
            for (int i = 0; i < 13; i++) a[i] = sImg[kk][ty + 16 * i];
            #pragma unroll
            for (int j = 0; j < 5; j++) bb[j] = sTxt[kk][tx + 16 * j];
            #pragma unroll
            for (int i = 0; i < 13; i++)
                #pragma unroll
                for (int j = 0; j < 5; j++)
                    acc[i][j] = fmaf(a[i], bb[j], acc[i][j]);
        }
    }
    __syncthreads();

    // ---- per-thread row max over its valid r-cols (j=4 valid iff tx<13) ----
    float rmax[13];
    const bool j4ok = (tx < 13);
    #pragma unroll
    for (int i = 0; i < 13; i++) {
        float m = fmaxf(fmaxf(acc[i][0], acc[i][1]), fmaxf(acc[i][2], acc[i][3]));
        if (j4ok) m = fmaxf(m, acc[i][4]);
        rmax[i] = m;
    }
    // reduce over tx (16-lane groups inside each warp)
    #pragma unroll
    for (int off = 8; off >= 1; off >>= 1) {
        #pragma unroll
        for (int i = 0; i < 13; i++)
            rmax[i] = fmaxf(rmax[i], __shfl_xor_sync(0xFFFFFFFFu, rmax[i], off));
    }
    if (tx == 0) {
        #pragma unroll
        for (int i = 0; i < 13; i++) {
            int q = ty + 16 * i;
            if (q < N1) rowRes[q] = rmax[i];
        }
    }

    // ---- per-thread col max over its valid q-rows (i=12 valid iff ty<4) ----
    const bool i12ok = (ty < 4);
    #pragma unroll
    for (int j = 0; j < 5; j++) {
        float m = acc[0][j];
        #pragma unroll
        for (int i = 1; i < 12; i++) m = fmaxf(m, acc[i][j]);
        if (i12ok) m = fmaxf(m, acc[12][j]);
        colPart[ty][tx + 16 * j] = m;
    }
    __syncthreads();

    // ---- final reductions ----
    float rsum = 0.0f, csum = 0.0f;
    if (tid < N1) rsum = rowRes[tid];
    if (tid < N2) {
        float m = colPart[0][tid];
        #pragma unroll
        for (int t = 1; t < 16; t++) m = fmaxf(m, colPart[t][tid]);
        csum = m;
    }
    // block sum
    #pragma unroll
    for (int off = 16; off >= 1; off >>= 1) {
        rsum += __shfl_xor_sync(0xFFFFFFFFu, rsum, off);
        csum += __shfl_xor_sync(0xFFFFFFFFu, csum, off);
    }
    int warp = tid >> 5, lane = tid & 31;
    if (lane == 0) { wrSum[warp] = rsum; wcSum[warp] = csum; }
    __syncthreads();
    if (tid == 0) {
        float R = 0.0f, C = 0.0f;
        #pragma unroll
        for (int w = 0; w < 8; w++) { R += wrSum[w]; C += wcSum[w]; }
        g_i2t[b * BATCH + c] = R * (1.0f / N1);
        g_t2i[c * BATCH + b] = C * (1.0f / N2);
    }
}

// CE with arange labels on both 96x96 logit matrices; out = 0.5*(ce1+ce2)
__global__ void ce_kernel(float* __restrict__ out) {
    const int t = threadIdx.x;
    float nll = 0.0f;
    if (t < 2 * BATCH) {
        const float* L = (t < BATCH) ? &g_i2t[t * BATCH] : &g_t2i[(t - BATCH) * BATCH];
        const int lab = (t < BATCH) ? t : (t - BATCH);
        float m = -INFINITY;
        for (int j = 0; j < BATCH; j++) m = fmaxf(m, L[j]);
        float s = 0.0f;
        for (int j = 0; j < BATCH; j++) s += expf(L[j] - m);
        nll = m + logf(s) - L[lab];
    }
    __shared__ float sh[2 * BATCH];
    if (t < 2 * BATCH) sh[t] = nll;
    __syncthreads();
    if (t == 0) {
        float s = 0.0f;
        for (int i = 0; i < 2 * BATCH; i++) s += sh[i];
        // 0.5 * (s1/96 + s2/96) == (s1+s2)/192
        out[0] = s * (1.0f / (2 * BATCH));
    }
}

extern "C" void kernel_launch(void* const* d_in, const int* in_sizes, int n_in,
                              void* d_out, int out_size) {
    const float* img = (const float*)d_in[0];   // [96, 196, 512] fp32
    const float* txt = (const float*)d_in[1];   // [96, 77, 512]  fp32
    float* out = (float*)d_out;                 // scalar fp32
    (void)in_sizes; (void)n_in; (void)out_size;

    dim3 grid(BATCH, BATCH);
    sim_kernel<<<grid, 256>>>(img, txt);
    ce_kernel<<<1, 2 * BATCH>>>(out);
}

// round 7
// speedup vs baseline: 2.1523x; 2.1523x over previous
#include <cuda_runtime.h>
#include <cuda_bf16.h>
#include <cstdint>
#include <math.h>

#define BB   96
#define NQ   196
#define NR   77
#define DIMK 512
#define KC   32            // k per chunk
#define NCHUNK (DIMK / KC) // 16
#define MT   13            // m16 tiles (208 rows)
#define NT   10            // n8 tiles (80 cols)
#define NWARP MT
#define NTHREAD (NWARP * 32)   // 416

// ---- smem layout (bytes). Row stride 80B (5x16B, conflict-free mod 8). ----
#define A_ROWB   80
#define A_SZ     (208 * A_ROWB)   // 16640
#define B_SZ     (80 * A_ROWB)    // 6400
#define OFF_AH   0
#define OFF_AL   (OFF_AH + A_SZ)
#define OFF_BH   (OFF_AL + A_SZ)
#define OFF_BL   (OFF_BH + B_SZ)
#define STAGE_SZ (OFF_BL + B_SZ)  // 46080
#define EP_OFF   (2 * STAGE_SZ)   // 92160
#define EP_ROW   (EP_OFF)               // 196 floats
#define EP_COL   (EP_OFF + 800)         // 13*80 floats
#define SMEM_BYTES (EP_OFF + 800 + 13 * 80 * 4 + 256)

__device__ __forceinline__ uint32_t smem_u32(const void* p) {
    uint32_t a;
    asm("{ .reg .u64 t; cvta.to.shared.u64 t, %1; cvt.u32.u64 %0, t; }" : "=r"(a) : "l"(p));
    return a;
}

#define CP_ASYNC16(d, s) asm volatile("cp.async.cg.shared.global [%0], [%1], 16;" :: "r"(d), "l"(s) : "memory")
#define CP_COMMIT()      asm volatile("cp.async.commit_group;" ::: "memory")
#define CP_WAIT1()       asm volatile("cp.async.wait_group 1;" ::: "memory")
#define CP_WAIT0()       asm volatile("cp.async.wait_group 0;" ::: "memory")

#define LDSM_X4(r0, r1, r2, r3, a) \
    asm volatile("ldmatrix.sync.aligned.m8n8.x4.shared.b16 {%0,%1,%2,%3}, [%4];" \
        : "=r"(r0), "=r"(r1), "=r"(r2), "=r"(r3) : "r"(a))

#define MMA_BF16(d, a, b) \
    asm volatile("mma.sync.aligned.m16n8k16.row.col.f32.bf16.bf16.f32 " \
        "{%0,%1,%2,%3},{%4,%5,%6,%7},{%8,%9},{%0,%1,%2,%3};" \
        : "+f"((d)[0]), "+f"((d)[1]), "+f"((d)[2]), "+f"((d)[3]) \
        : "r"((a)[0]), "r"((a)[1]), "r"((a)[2]), "r"((a)[3]), "r"((b)[0]), "r"((b)[1]))

// ---------------- global scratch ----------------
__device__ __nv_bfloat16 g_img_hi[BB * NQ * DIMK];
__device__ __nv_bfloat16 g_img_lo[BB * NQ * DIMK];
__device__ __nv_bfloat16 g_txt_hi[BB * NR * DIMK];
__device__ __nv_bfloat16 g_txt_lo[BB * NR * DIMK];
__device__ float g_i2t[BB * BB];
__device__ float g_t2i[BB * BB];
__device__ float g_nll[2 * BB];

// ---------------- prep: fp32 -> bf16 hi/lo split ----------------
__global__ void prep_kernel(const float* __restrict__ img, const float* __restrict__ txt) {
    const long long TI = (long long)BB * NQ * DIMK;
    const long long TT = (long long)BB * NR * DIMK;
    long long i = (long long)blockIdx.x * blockDim.x + threadIdx.x;
    if (i < TI) {
        float x = img[i];
        __nv_bfloat16 h = __float2bfloat16(x);
        g_img_hi[i] = h;
        g_img_lo[i] = __float2bfloat16(x - __bfloat162float(h));
    } else if (i < TI + TT) {
        long long j = i - TI;
        float x = txt[j];
        __nv_bfloat16 h = __float2bfloat16(x);
        g_txt_hi[j] = h;
        g_txt_lo[j] = __float2bfloat16(x - __bfloat162float(h));
    }
}

// ---------------- chunk loader ----------------
__device__ __forceinline__ void load_chunk(uint32_t smb, uint32_t stage_off,
                                           int b, int c, int k0, int tid) {
    // A: 196 rows x 4 chunks(16B) x 2 halves
    for (int idx = tid; idx < NQ * 8; idx += NTHREAD) {
        int q = idx >> 3, rem = idx & 7, hv = rem >> 2, ch = rem & 3;
        const __nv_bfloat16* base = hv ? g_img_lo : g_img_hi;
        const char* src = (const char*)(base + (size_t)(b * NQ + q) * DIMK + k0) + ch * 16;
        uint32_t dst = smb + stage_off + (hv ? OFF_AL : OFF_AH) + q * A_ROWB + ch * 16;
        CP_ASYNC16(dst, src);
    }
    // B: 77 rows x 4 chunks x 2 halves
    for (int idx = tid; idx < NR * 8; idx += NTHREAD) {
        int n = idx >> 3, rem = idx & 7, hv = rem >> 2, ch = rem & 3;
        const __nv_bfloat16* base = hv ? g_txt_lo : g_txt_hi;
        const char* src = (const char*)(base + (size_t)(c * NR + n) * DIMK + k0) + ch * 16;
        uint32_t dst = smb + stage_off + (hv ? OFF_BL : OFF_BH) + n * A_ROWB + ch * 16;
        CP_ASYNC16(dst, src);
    }
}

// ---------------- main MMA kernel: one CTA per (b, c) ----------------
__global__ __launch_bounds__(NTHREAD, 1) void sim_kernel() {
    extern __shared__ __align__(128) char smp[];
    const uint32_t smb = smem_u32(smp);
    const int tid = threadIdx.x;
    const int w = tid >> 5, lane = tid & 31;
    const int b = blockIdx.x, c = blockIdx.y;

    // zero pad rows (A rows 196..207, B rows 77..79; both halves, both stages; 64 valid bytes/row)
    for (int idx = tid; idx < 2 * 2 * 12 * 16; idx += NTHREAD) {
        int s = idx / (2 * 12 * 16), rem = idx % (2 * 12 * 16);
        int hv = rem / (12 * 16); rem %= 12 * 16;
        int row = 196 + rem / 16, word = rem % 16;
        *(uint32_t*)(smp + s * STAGE_SZ + (hv ? OFF_AL : OFF_AH) + row * A_ROWB + word * 4) = 0;
    }
    for (int idx = tid; idx < 2 * 2 * 3 * 16; idx += NTHREAD) {
        int s = idx / (2 * 3 * 16), rem = idx % (2 * 3 * 16);
        int hv = rem / (3 * 16); rem %= 3 * 16;
        int row = 77 + rem / 16, word = rem % 16;
        *(uint32_t*)(smp + s * STAGE_SZ + (hv ? OFF_BL : OFF_BH) + row * A_ROWB + word * 4) = 0;
    }

    // ldmatrix per-lane address offsets (within a stage)
    const int j = lane >> 3, r8 = lane & 7;
    // A x4: matrix j: row = w*16 + r8 + (j&1)*8, kbyte = (j>>1)*16
    const uint32_t aoff = (uint32_t)((w * 16 + r8 + (j & 1) * 8) * A_ROWB + (j >> 1) * 16);
    // B x4 pair p (n-tiles 2p,2p+1): row = (2p + (j>>1))*8 + r8, kbyte = (j&1)*16
    const uint32_t boff0 = (uint32_t)(((j >> 1) * 8 + r8) * A_ROWB + (j & 1) * 16);

    float acc[NT * 4];
    #pragma unroll
    for (int i = 0; i < NT * 4; i++) acc[i] = 0.0f;

    // prologue
    load_chunk(smb, 0, b, c, 0, tid);
    CP_COMMIT();

    for (int ck = 0; ck < NCHUNK; ck++) {
        if (ck + 1 < NCHUNK) {
            load_chunk(smb, (uint32_t)((ck + 1) & 1) * STAGE_SZ, b, c, (ck + 1) * KC, tid);
            CP_COMMIT();
            CP_WAIT1();
        } else {
            CP_WAIT0();
        }
        __syncthreads();

        const uint32_t st = smb + (uint32_t)(ck & 1) * STAGE_SZ;
        #pragma unroll
        for (int ks = 0; ks < 2; ks++) {
            const uint32_t kb = ks * 32;
            uint32_t ah[4], al[4], bh[2 * NT], bl[2 * NT];
            LDSM_X4(ah[0], ah[1], ah[2], ah[3], st + OFF_AH + aoff + kb);
            LDSM_X4(al[0], al[1], al[2], al[3], st + OFF_AL + aoff + kb);
            #pragma unroll
            for (int p = 0; p < 5; p++) {
                LDSM_X4(bh[4 * p], bh[4 * p + 1], bh[4 * p + 2], bh[4 * p + 3],
                        st + OFF_BH + boff0 + (uint32_t)(p * 16 * A_ROWB) + kb);
                LDSM_X4(bl[4 * p], bl[4 * p + 1], bl[4 * p + 2], bl[4 * p + 3],
                        st + OFF_BL + boff0 + (uint32_t)(p * 16 * A_ROWB) + kb);
            }
            #pragma unroll
            for (int n = 0; n < NT; n++) {
                MMA_BF16(acc + n * 4, ah, bh + n * 2);
                MMA_BF16(acc + n * 4, ah, bl + n * 2);
                MMA_BF16(acc + n * 4, al, bh + n * 2);
            }
        }
        __syncthreads();
    }

    // -------- epilogue --------
    float* rowRes  = (float*)(smp + EP_ROW);
    float* colPart = (float*)(smp + EP_COL);
    const int r0 = w * 16 + (lane >> 2);
    const int r1 = r0 + 8;

    // rowmax (mask pad cols >= 77)
    float rm0 = -INFINITY, rm1 = -INFINITY;
    #pragma unroll
    for (int n = 0; n < NT; n++) {
        #pragma unroll
        for (int e = 0; e < 2; e++) {
            int col = n * 8 + ((lane & 3) << 1) + e;
            if (col < NR) {
                rm0 = fmaxf(rm0, acc[n * 4 + e]);
                rm1 = fmaxf(rm1, acc[n * 4 + 2 + e]);
            }
        }
    }
    rm0 = fmaxf(rm0, __shfl_xor_sync(0xFFFFFFFFu, rm0, 1));
    rm0 = fmaxf(rm0, __shfl_xor_sync(0xFFFFFFFFu, rm0, 2));
    rm1 = fmaxf(rm1, __shfl_xor_sync(0xFFFFFFFFu, rm1, 1));
    rm1 = fmaxf(rm1, __shfl_xor_sync(0xFFFFFFFFu, rm1, 2));
    if ((lane & 3) == 0) {
        if (r0 < NQ) rowRes[r0] = rm0;
        if (r1 < NQ) rowRes[r1] = rm1;
    }

    // colmax (mask pad rows >= 196)
    #pragma unroll
    for (int n = 0; n < NT; n++) {
        #pragma unroll
        for (int e = 0; e < 2; e++) {
            float v = -INFINITY;
            if (r0 < NQ) v = acc[n * 4 + e];
            if (r1 < NQ) v = fmaxf(v, acc[n * 4 + 2 + e]);
            v = fmaxf(v, __shfl_xor_sync(0xFFFFFFFFu, v, 4));
            v = fmaxf(v, __shfl_xor_sync(0xFFFFFFFFu, v, 8));
            v = fmaxf(v, __shfl_xor_sync(0xFFFFFFFFu, v, 16));
            if (lane < 4) colPart[w * 80 + n * 8 + lane * 2 + e] = v;
        }
    }
    __syncthreads();

    if (w == 0) {  // i2t: mean of rowmax
        float s = 0.0f;
        for (int q = lane; q < NQ; q += 32) s += rowRes[q];
        #pragma unroll
        for (int off = 16; off >= 1; off >>= 1) s += __shfl_xor_sync(0xFFFFFFFFu, s, off);
        if (lane == 0) g_i2t[b * BB + c] = s * (1.0f / NQ);
    }
    if (w == 1) {  // t2i: mean of colmax
        float s = 0.0f;
        for (int col = lane; col < NR; col += 32) {
            float m = colPart[col];
            #pragma unroll
            for (int ww = 1; ww < NWARP; ww++) m = fmaxf(m, colPart[ww * 80 + col]);
            s += m;
        }
        #pragma unroll
        for (int off = 16; off >= 1; off >>= 1) s += __shfl_xor_sync(0xFFFFFFFFu, s, off);
        if (lane == 0) g_t2i[c * BB + b] = s * (1.0f / NR);
    }
}

// ---------------- CE: one warp per logit row ----------------
__global__ void ce1_kernel() {
    int gw = (blockIdx.x * blockDim.x + threadIdx.x) >> 5;  // 0..191
    int lane = threadIdx.x & 31;
    const float* L = (gw < BB) ? (g_i2t + gw * BB) : (g_t2i + (gw - BB) * BB);
    int lab = (gw < BB) ? gw : gw - BB;
    float v0 = L[lane], v1 = L[lane + 32], v2 = L[lane + 64];
    float m = fmaxf(v0, fmaxf(v1, v2));
    #pragma unroll
    for (int off = 16; off >= 1; off >>= 1) m = fmaxf(m, __shfl_xor_sync(0xFFFFFFFFu, m, off));
    float s = expf(v0 - m) + expf(v1 - m) + expf(v2 - m);
    #pragma unroll
    for (int off = 16; off >= 1; off >>= 1) s += __shfl_xor_sync(0xFFFFFFFFu, s, off);
    if (lane == 0) g_nll[gw] = m + logf(s) - L[lab];
}

__global__ void ce2_kernel(float* __restrict__ out) {
    int t = threadIdx.x;
    float v = (t < 2 * BB) ? g_nll[t] : 0.0f;
    #pragma unroll
    for (int off = 16; off >= 1; off >>= 1) v += __shfl_xor_sync(0xFFFFFFFFu, v, off);
    __shared__ float sh[8];
    if ((t & 31) == 0) sh[t >> 5] = v;
    __syncthreads();
    if (t == 0) {
        float s = 0.0f;
        #pragma unroll
        for (int ww = 0; ww < 8; ww++) s += sh[ww];
        out[0] = s * (1.0f / (2.0f * BB));
    }
}

extern "C" void kernel_launch(void* const* d_in, const int* in_sizes, int n_in,
                              void* d_out, int out_size) {
    const float* img = (const float*)d_in[0];
    const float* txt = (const float*)d_in[1];
    float* out = (float*)d_out;
    (void)in_sizes; (void)n_in; (void)out_size;

    cudaFuncSetAttribute(sim_kernel, cudaFuncAttributeMaxDynamicSharedMemorySize, SMEM_BYTES);

    long long total = (long long)BB * NQ * DIMK + (long long)BB * NR * DIMK;
    prep_kernel<<<(unsigned)((total + 255) / 256), 256>>>(img, txt);

    dim3 grid(BB, BB);
    sim_kernel<<<grid, NTHREAD, SMEM_BYTES>>>();

    ce1_kernel<<<(2 * BB * 32) / 256, 256>>>();
    ce2_kernel<<<1, 256>>>(out);
}

// round 9
// speedup vs baseline: 3.1584x; 1.4675x over previous
#include <cuda_runtime.h>
#include <cuda_fp16.h>
#include <cstdint>
#include <math.h>

#define BB   96
#define NQ   196
#define NR   77
#define DIMK 512
#define KC   64            // k per chunk
#define NCHUNK (DIMK / KC) // 8
#define MT   13            // m16 tiles (208 rows)
#define NT   10            // n8 tiles (80 cols)
#define NWARP MT
#define NTHREAD (NWARP * 32)   // 416

// ---- smem layout. Row stride 144B (9x16B, conflict-free ldmatrix). ----
#define RB       144
#define A_SZ     (208 * RB)       // 29952
#define B_SZ     (80 * RB)        // 11520
#define OFF_AH   0
#define OFF_AL   (OFF_AH + A_SZ)
#define OFF_B    (OFF_AL + A_SZ)
#define STAGE_SZ (OFF_B + B_SZ)   // 71424
#define SMEM_BYTES (2 * STAGE_SZ) // 142848
// epilogue scratch reuses stage0 after the final compute sync
#define EP_ROW   0                 // 196 floats
#define EP_COL   1024              // 13*80 floats

__device__ __forceinline__ uint32_t smem_u32(const void* p) {
    uint32_t a;
    asm("{ .reg .u64 t; cvta.to.shared.u64 t, %1; cvt.u32.u64 %0, t; }" : "=r"(a) : "l"(p));
    return a;
}

#define CP_ASYNC16(d, s) asm volatile("cp.async.cg.shared.global [%0], [%1], 16;" :: "r"(d), "l"(s) : "memory")
#define CP_COMMIT()      asm volatile("cp.async.commit_group;" ::: "memory")
#define CP_WAIT1()       asm volatile("cp.async.wait_group 1;" ::: "memory")
#define CP_WAIT0()       asm volatile("cp.async.wait_group 0;" ::: "memory")

#define LDSM_X4(r0, r1, r2, r3, a) \
    asm volatile("ldmatrix.sync.aligned.m8n8.x4.shared.b16 {%0,%1,%2,%3}, [%4];" \
        : "=r"(r0), "=r"(r1), "=r"(r2), "=r"(r3) : "r"(a))

#define MMA_F16(d, a, b) \
    asm volatile("mma.sync.aligned.m16n8k16.row.col.f32.f16.f16.f32 " \
        "{%0,%1,%2,%3},{%4,%5,%6,%7},{%8,%9},{%0,%1,%2,%3};" \
        : "+f"((d)[0]), "+f"((d)[1]), "+f"((d)[2]), "+f"((d)[3]) \
        : "r"((a)[0]), "r"((a)[1]), "r"((a)[2]), "r"((a)[3]), "r"((b)[0]), "r"((b)[1]))

// ---------------- global scratch ----------------
__device__ __half g_img_hi[BB * NQ * DIMK];
__device__ __half g_img_lo[BB * NQ * DIMK];
__device__ __half g_txt_hi[BB * NR * DIMK];
__device__ float g_i2t[BB * BB];
__device__ float g_t2i[BB * BB];
__device__ float g_nll[2 * BB];

// ---------------- prep: img fp32 -> fp16 hi/lo split; txt -> fp16 ----------------
__global__ void prep_kernel(const float* __restrict__ img, const float* __restrict__ txt) {
    const long long TI = (long long)BB * NQ * DIMK;
    const long long TT = (long long)BB * NR * DIMK;
    long long i = (long long)blockIdx.x * blockDim.x + threadIdx.x;
    if (i < TI) {
        float x = img[i];
        __half h = __float2half(x);
        g_img_hi[i] = h;
        g_img_lo[i] = __float2half(x - __half2float(h));
    } else if (i < TI + TT) {
        long long j = i - TI;
        g_txt_hi[j] = __float2half(txt[j]);
    }
}

// ---------------- chunk loader ----------------
__device__ __forceinline__ void load_chunk(uint32_t smb, uint32_t stage_off,
                                           int b, int c, int k0, int tid) {
    // A: 196 rows x 2 halves x 8 segs of 16B
    for (int idx = tid; idx < NQ * 16; idx += NTHREAD) {
        int q = idx >> 4, rem = idx & 15, hv = rem >> 3, seg = rem & 7;
        const __half* base = hv ? g_img_lo : g_img_hi;
        const char* src = (const char*)(base + (size_t)(b * NQ + q) * DIMK + k0) + seg * 16;
        uint32_t dst = smb + stage_off + (hv ? OFF_AL : OFF_AH) + q * RB + seg * 16;
        CP_ASYNC16(dst, src);
    }
    // B: 77 rows x 8 segs
    for (int idx = tid; idx < NR * 8; idx += NTHREAD) {
        int n = idx >> 3, seg = idx & 7;
        const char* src = (const char*)(g_txt_hi + (size_t)(c * NR + n) * DIMK + k0) + seg * 16;
        uint32_t dst = smb + stage_off + OFF_B + n * RB + seg * 16;
        CP_ASYNC16(dst, src);
    }
}

// ---------------- main MMA kernel: one CTA per (b, c) ----------------
__global__ __launch_bounds__(NTHREAD, 1) void sim_kernel() {
    extern __shared__ __align__(128) char smp[];
    const uint32_t smb = smem_u32(smp);
    const int tid = threadIdx.x;
    const int w = tid >> 5, lane = tid & 31;
    const int b = blockIdx.x, c = blockIdx.y;

    // zero pad rows (A rows 196..207 hi+lo, B rows 77..79; both stages; full 36 words)
    for (int idx = tid; idx < 2 * 2 * 12 * 36; idx += NTHREAD) {
        int s = idx / (2 * 12 * 36), rem = idx % (2 * 12 * 36);
        int hv = rem / (12 * 36); rem %= 12 * 36;
        int row = 196 + rem / 36, word = rem % 36;
        *(uint32_t*)(smp + s * STAGE_SZ + (hv ? OFF_AL : OFF_AH) + row * RB + word * 4) = 0;
    }
    for (int idx = tid; idx < 2 * 3 * 36; idx += NTHREAD) {
        int s = idx / (3 * 36), rem = idx % (3 * 36);
        int row = 77 + rem / 36, word = rem % 36;
        *(uint32_t*)(smp + s * STAGE_SZ + OFF_B + row * RB + word * 4) = 0;
    }

    // ldmatrix per-lane address offsets (within a stage)
    const int j = lane >> 3, r8 = lane & 7;
    const uint32_t aoff  = (uint32_t)((w * 16 + r8 + (j & 1) * 8) * RB + (j >> 1) * 16);
    const uint32_t boff0 = (uint32_t)(((j >> 1) * 8 + r8) * RB + (j & 1) * 16);

    float acc[NT * 4];
    #pragma unroll
    for (int i = 0; i < NT * 4; i++) acc[i] = 0.0f;

    // prologue
    load_chunk(smb, 0, b, c, 0, tid);
    CP_COMMIT();

    for (int ck = 0; ck < NCHUNK; ck++) {
        if (ck + 1 < NCHUNK) {
            load_chunk(smb, (uint32_t)((ck + 1) & 1) * STAGE_SZ, b, c, (ck + 1) * KC, tid);
            CP_COMMIT();
            CP_WAIT1();
        } else {
            CP_WAIT0();
        }
        __syncthreads();

        const uint32_t st = smb + (uint32_t)(ck & 1) * STAGE_SZ;
        #pragma unroll
        for (int ks = 0; ks < 4; ks++) {
            const uint32_t kb = ks * 32;
            uint32_t ah[4], al[4], bh[2 * NT];
            LDSM_X4(ah[0], ah[1], ah[2], ah[3], st + OFF_AH + aoff + kb);
            LDSM_X4(al[0], al[1], al[2], al[3], st + OFF_AL + aoff + kb);
            #pragma unroll
            for (int p = 0; p < 5; p++) {
                LDSM_X4(bh[4 * p], bh[4 * p + 1], bh[4 * p + 2], bh[4 * p + 3],
                        st + OFF_B + boff0 + (uint32_t)(p * 16 * RB) + kb);
            }
            #pragma unroll
            for (int n = 0; n < NT; n++) {
                MMA_F16(acc + n * 4, ah, bh + n * 2);
                MMA_F16(acc + n * 4, al, bh + n * 2);
            }
        }
        __syncthreads();
    }

    // -------- epilogue --------
    float* rowRes  = (float*)(smp + EP_ROW);
    float* colPart = (float*)(smp + EP_COL);
    const int r0 = w * 16 + (lane >> 2);
    const int r1 = r0 + 8;

    // rowmax (mask pad cols >= 77)
    float rm0 = -INFINITY, rm1 = -INFINITY;
    #pragma unroll
    for (int n = 0; n < NT; n++) {
        #pragma unroll
        for (int e = 0; e < 2; e++) {
            int col = n * 8 + ((lane & 3) << 1) + e;
            if (col < NR) {
                rm0 = fmaxf(rm0, acc[n * 4 + e]);
                rm1 = fmaxf(rm1, acc[n * 4 + 2 + e]);
            }
        }
    }
    rm0 = fmaxf(rm0, __shfl_xor_sync(0xFFFFFFFFu, rm0, 1));
    rm0 = fmaxf(rm0, __shfl_xor_sync(0xFFFFFFFFu, rm0, 2));
    rm1 = fmaxf(rm1, __shfl_xor_sync(0xFFFFFFFFu, rm1, 1));
    rm1 = fmaxf(rm1, __shfl_xor_sync(0xFFFFFFFFu, rm1, 2));
    if ((lane & 3) == 0) {
        if (r0 < NQ) rowRes[r0] = rm0;
        if (r1 < NQ) rowRes[r1] = rm1;
    }

    // colmax (mask pad rows >= 196)
    #pragma unroll
    for (int n = 0; n < NT; n++) {
        #pragma unroll
        for (int e = 0; e < 2; e++) {
            float v = -INFINITY;
            if (r0 < NQ) v = acc[n * 4 + e];
            if (r1 < NQ) v = fmaxf(v, acc[n * 4 + 2 + e]);
            v = fmaxf(v, __shfl_xor_sync(0xFFFFFFFFu, v, 4));
            v = fmaxf(v, __shfl_xor_sync(0xFFFFFFFFu, v, 8));
            v = fmaxf(v, __shfl_xor_sync(0xFFFFFFFFu, v, 16));
            if (lane < 4) colPart[w * 80 + n * 8 + lane * 2 + e] = v;
        }
    }
    __syncthreads();

    if (w == 0) {  // i2t: mean of rowmax
        float s = 0.0f;
        for (int q = lane; q < NQ; q += 32) s += rowRes[q];
        #pragma unroll
        for (int off = 16; off >= 1; off >>= 1) s += __shfl_xor_sync(0xFFFFFFFFu, s, off);
        if (lane == 0) g_i2t[b * BB + c] = s * (1.0f / NQ);
    }
    if (w == 1) {  // t2i: mean of colmax
        float s = 0.0f;
        for (int col = lane; col < NR; col += 32) {
            float m = colPart[col];
            #pragma unroll
            for (int ww = 1; ww < NWARP; ww++) m = fmaxf(m, colPart[ww * 80 + col]);
            s += m;
        }
        #pragma unroll
        for (int off = 16; off >= 1; off >>= 1) s += __shfl_xor_sync(0xFFFFFFFFu, s, off);
        if (lane == 0) g_t2i[c * BB + b] = s * (1.0f / NR);
    }
}

// ---------------- CE: one warp per logit row ----------------
__global__ void ce1_kernel() {
    int gw = (blockIdx.x * blockDim.x + threadIdx.x) >> 5;  // 0..191
    int lane = threadIdx.x & 31;
    const float* L = (gw < BB) ? (g_i2t + gw * BB) : (g_t2i + (gw - BB) * BB);
    int lab = (gw < BB) ? gw : gw - BB;
    float v0 = L[lane], v1 = L[lane + 32], v2 = L[lane + 64];
    float m = fmaxf(v0, fmaxf(v1, v2));
    #pragma unroll
    for (int off = 16; off >= 1; off >>= 1) m = fmaxf(m, __shfl_xor_sync(0xFFFFFFFFu, m, off));
    float s = expf(v0 - m) + expf(v1 - m) + expf(v2 - m);
    #pragma unroll
    for (int off = 16; off >= 1; off >>= 1) s += __shfl_xor_sync(0xFFFFFFFFu, s, off);
    if (lane == 0) g_nll[gw] = m + logf(s) - L[lab];
}

__global__ void ce2_kernel(float* __restrict__ out) {
    int t = threadIdx.x;
    float v = (t < 2 * BB) ? g_nll[t] : 0.0f;
    #pragma unroll
    for (int off = 16; off >= 1; off >>= 1) v += __shfl_xor_sync(0xFFFFFFFFu, v, off);
    __shared__ float sh[8];
    if ((t & 31) == 0) sh[t >> 5] = v;
    __syncthreads();
    if (t == 0) {
        float s = 0.0f;
        #pragma unroll
        for (int ww = 0; ww < 8; ww++) s += sh[ww];
        out[0] = s * (1.0f / (2.0f * BB));
    }
}

extern "C" void kernel_launch(void* const* d_in, const int* in_sizes, int n_in,
                              void* d_out, int out_size) {
    const float* img = (const float*)d_in[0];
    const float* txt = (const float*)d_in[1];
    float* out = (float*)d_out;
    (void)in_sizes; (void)n_in; (void)out_size;

    cudaFuncSetAttribute(sim_kernel, cudaFuncAttributeMaxDynamicSharedMemorySize, SMEM_BYTES);

    long long total = (long long)BB * NQ * DIMK + (long long)BB * NR * DIMK;
    prep_kernel<<<(unsigned)((total + 255) / 256), 256>>>(img, txt);

    dim3 grid(BB, BB);
    sim_kernel<<<grid, NTHREAD, SMEM_BYTES>>>();

    ce1_kernel<<<(2 * BB * 32) / 256, 256>>>();
    ce2_kernel<<<1, 256>>>(out);
}

// round 10
// speedup vs baseline: 4.9377x; 1.5633x over previous
#include <cuda_runtime.h>
#include <cuda_fp16.h>
#include <cstdint>
#include <math.h>

#define BB   96
#define NQ   196
#define NR   77
#define DIMK 512
#define KC   64            // k per chunk
#define NCHUNK (DIMK / KC) // 8
#define MT   13            // m16 tiles (208 rows)
#define NT   10            // n8 tiles (80 cols)
#define NWARP MT
#define NTHREAD (NWARP * 32)   // 416
#define NSTAGE 3

// ---- smem layout. Row stride 144B (9x16B, conflict-free ldmatrix). ----
#define RB       144
#define A_SZ     (208 * RB)       // 29952
#define B_SZ     (80 * RB)        // 11520
#define OFF_A    0
#define OFF_B    (OFF_A + A_SZ)
#define STAGE_SZ (OFF_B + B_SZ)   // 41472
#define SMEM_BYTES (NSTAGE * STAGE_SZ) // 124416
// epilogue scratch reuses stage0 (its last producer, chunk 6, is fenced by iter-7 sync)
#define EP_ROW   0                 // 196 floats
#define EP_COL   1024              // 13*80 floats

__device__ __forceinline__ uint32_t smem_u32(const void* p) {
    uint32_t a;
    asm("{ .reg .u64 t; cvta.to.shared.u64 t, %1; cvt.u32.u64 %0, t; }" : "=r"(a) : "l"(p));
    return a;
}

#define CP_ASYNC16(d, s) asm volatile("cp.async.cg.shared.global [%0], [%1], 16;" :: "r"(d), "l"(s) : "memory")
#define CP_COMMIT()      asm volatile("cp.async.commit_group;" ::: "memory")
#define CP_WAIT1()       asm volatile("cp.async.wait_group 1;" ::: "memory")
#define CP_WAIT0()       asm volatile("cp.async.wait_group 0;" ::: "memory")

#define LDSM_X4(r0, r1, r2, r3, a) \
    asm volatile("ldmatrix.sync.aligned.m8n8.x4.shared.b16 {%0,%1,%2,%3}, [%4];" \
        : "=r"(r0), "=r"(r1), "=r"(r2), "=r"(r3) : "r"(a))

#define MMA_F16(d, a, b) \
    asm volatile("mma.sync.aligned.m16n8k16.row.col.f32.f16.f16.f32 " \
        "{%0,%1,%2,%3},{%4,%5,%6,%7},{%8,%9},{%0,%1,%2,%3};" \
        : "+f"((d)[0]), "+f"((d)[1]), "+f"((d)[2]), "+f"((d)[3]) \
        : "r"((a)[0]), "r"((a)[1]), "r"((a)[2]), "r"((a)[3]), "r"((b)[0]), "r"((b)[1]))

// ---------------- global scratch ----------------
__device__ __half g_img[BB * NQ * DIMK];
__device__ __half g_txt[BB * NR * DIMK];
__device__ float g_i2t[BB * BB];
__device__ float g_t2i[BB * BB];
__device__ float g_nll[2 * BB];

// ---------------- prep: fp32 -> fp16 ----------------
__global__ void prep_kernel(const float* __restrict__ img, const float* __restrict__ txt) {
    const long long TI = (long long)BB * NQ * DIMK;
    const long long TT = (long long)BB * NR * DIMK;
    long long i = (long long)blockIdx.x * blockDim.x + threadIdx.x;
    if (i < TI) {
        g_img[i] = __float2half(img[i]);
    } else if (i < TI + TT) {
        long long j = i - TI;
        g_txt[j] = __float2half(txt[j]);
    }
}

// ---------------- chunk loader ----------------
__device__ __forceinline__ void load_chunk(uint32_t smb, uint32_t stage_off,
                                           int b, int c, int k0, int tid) {
    // A: 196 rows x 8 segs of 16B
    for (int idx = tid; idx < NQ * 8; idx += NTHREAD) {
        int q = idx >> 3, seg = idx & 7;
        const char* src = (const char*)(g_img + (size_t)(b * NQ + q) * DIMK + k0) + seg * 16;
        uint32_t dst = smb + stage_off + OFF_A + q * RB + seg * 16;
        CP_ASYNC16(dst, src);
    }
    // B: 77 rows x 8 segs
    for (int idx = tid; idx < NR * 8; idx += NTHREAD) {
        int n = idx >> 3, seg = idx & 7;
        const char* src = (const char*)(g_txt + (size_t)(c * NR + n) * DIMK + k0) + seg * 16;
        uint32_t dst = smb + stage_off + OFF_B + n * RB + seg * 16;
        CP_ASYNC16(dst, src);
    }
}

// ---------------- main MMA kernel: one CTA per (b, c) ----------------
__global__ __launch_bounds__(NTHREAD, 1) void sim_kernel() {
    extern __shared__ __align__(128) char smp[];
    const uint32_t smb = smem_u32(smp);
    const int tid = threadIdx.x;
    const int w = tid >> 5, lane = tid & 31;
    const int b = blockIdx.x, c = blockIdx.y;

    // zero pad rows (A rows 196..207, B rows 77..79; all stages; full 36 words)
    for (int idx = tid; idx < NSTAGE * 12 * 36; idx += NTHREAD) {
        int s = idx / (12 * 36), rem = idx % (12 * 36);
        int row = 196 + rem / 36, word = rem % 36;
        *(uint32_t*)(smp + s * STAGE_SZ + OFF_A + row * RB + word * 4) = 0;
    }
    for (int idx = tid; idx < NSTAGE * 3 * 36; idx += NTHREAD) {
        int s = idx / (3 * 36), rem = idx % (3 * 36);
        int row = 77 + rem / 36, word = rem % 36;
        *(uint32_t*)(smp + s * STAGE_SZ + OFF_B + row * RB + word * 4) = 0;
    }

    // ldmatrix per-lane address offsets (within a stage)
    const int j = lane >> 3, r8 = lane & 7;
    const uint32_t aoff  = (uint32_t)((w * 16 + r8 + (j & 1) * 8) * RB + (j >> 1) * 16);
    const uint32_t boff0 = (uint32_t)(((j >> 1) * 8 + r8) * RB + (j & 1) * 16);

    float acc[NT * 4];
    #pragma unroll
    for (int i = 0; i < NT * 4; i++) acc[i] = 0.0f;

    // prologue: 2 chunks in flight
    load_chunk(smb, 0 * STAGE_SZ, b, c, 0, tid);
    CP_COMMIT();
    load_chunk(smb, 1 * STAGE_SZ, b, c, KC, tid);
    CP_COMMIT();

    for (int ck = 0; ck < NCHUNK; ck++) {
        if (ck < NCHUNK - 1) CP_WAIT1();   // chunk ck landed (ck+1 may be pending)
        else                 CP_WAIT0();
        __syncthreads();                   // also fences compute(ck-1) on all warps
        if (ck + 2 < NCHUNK) {
            load_chunk(smb, (uint32_t)((ck + 2) % NSTAGE) * STAGE_SZ, b, c, (ck + 2) * KC, tid);
            CP_COMMIT();
        }

        const uint32_t st = smb + (uint32_t)(ck % NSTAGE) * STAGE_SZ;
        #pragma unroll
        for (int ks = 0; ks < 4; ks++) {
            const uint32_t kb = ks * 32;
            uint32_t ah[4], bh[2 * NT];
            LDSM_X4(ah[0], ah[1], ah[2], ah[3], st + OFF_A + aoff + kb);
            #pragma unroll
            for (int p = 0; p < 5; p++) {
                LDSM_X4(bh[4 * p], bh[4 * p + 1], bh[4 * p + 2], bh[4 * p + 3],
                        st + OFF_B + boff0 + (uint32_t)(p * 16 * RB) + kb);
            }
            #pragma unroll
            for (int n = 0; n < NT; n++) {
                MMA_F16(acc + n * 4, ah, bh + n * 2);
            }
        }
    }

    // -------- epilogue (stage0 reuse: safe, see header note) --------
    float* rowRes  = (float*)(smp + EP_ROW);
    float* colPart = (float*)(smp + EP_COL);
    const int r0 = w * 16 + (lane >> 2);
    const int r1 = r0 + 8;

    // rowmax (mask pad cols >= 77)
    float rm0 = -INFINITY, rm1 = -INFINITY;
    #pragma unroll
    for (int n = 0; n < NT; n++) {
        #pragma unroll
        for (int e = 0; e < 2; e++) {
            int col = n * 8 + ((lane & 3) << 1) + e;
            if (col < NR) {
                rm0 = fmaxf(rm0, acc[n * 4 + e]);
                rm1 = fmaxf(rm1, acc[n * 4 + 2 + e]);
            }
        }
    }
    rm0 = fmaxf(rm0, __shfl_xor_sync(0xFFFFFFFFu, rm0, 1));
    rm0 = fmaxf(rm0, __shfl_xor_sync(0xFFFFFFFFu, rm0, 2));
    rm1 = fmaxf(rm1, __shfl_xor_sync(0xFFFFFFFFu, rm1, 1));
    rm1 = fmaxf(rm1, __shfl_xor_sync(0xFFFFFFFFu, rm1, 2));
    if ((lane & 3) == 0) {
        if (r0 < NQ) rowRes[r0] = rm0;
        if (r1 < NQ) rowRes[r1] = rm1;
    }

    // colmax (mask pad rows >= 196)
    #pragma unroll
    for (int n = 0; n < NT; n++) {
        #pragma unroll
        for (int e = 0; e < 2; e++) {
            float v = -INFINITY;
            if (r0 < NQ) v = acc[n * 4 + e];
            if (r1 < NQ) v = fmaxf(v, acc[n * 4 + 2 + e]);
            v = fmaxf(v, __shfl_xor_sync(0xFFFFFFFFu, v, 4));
            v = fmaxf(v, __shfl_xor_sync(0xFFFFFFFFu, v, 8));
            v = fmaxf(v, __shfl_xor_sync(0xFFFFFFFFu, v, 16));
            if (lane < 4) colPart[w * 80 + n * 8 + lane * 2 + e] = v;
        }
    }
    __syncthreads();

    if (w == 0) {  // i2t: mean of rowmax
        float s = 0.0f;
        for (int q = lane; q < NQ; q += 32) s += rowRes[q];
        #pragma unroll
        for (int off = 16; off >= 1; off >>= 1) s += __shfl_xor_sync(0xFFFFFFFFu, s, off);
        if (lane == 0) g_i2t[b * BB + c] = s * (1.0f / NQ);
    }
    if (w == 1) {  // t2i: mean of colmax
        float s = 0.0f;
        for (int col = lane; col < NR; col += 32) {
            float m = colPart[col];
            #pragma unroll
            for (int ww = 1; ww < NWARP; ww++) m = fmaxf(m, colPart[ww * 80 + col]);
            s += m;
        }
        #pragma unroll
        for (int off = 16; off >= 1; off >>= 1) s += __shfl_xor_sync(0xFFFFFFFFu, s, off);
        if (lane == 0) g_t2i[c * BB + b] = s * (1.0f / NR);
    }
}

// ---------------- CE: one warp per logit row ----------------
__global__ void ce1_kernel() {
    int gw = (blockIdx.x * blockDim.x + threadIdx.x) >> 5;  // 0..191
    int lane = threadIdx.x & 31;
    const float* L = (gw < BB) ? (g_i2t + gw * BB) : (g_t2i + (gw - BB) * BB);
    int lab = (gw < BB) ? gw : gw - BB;
    float v0 = L[lane], v1 = L[lane + 32], v2 = L[lane + 64];
    float m = fmaxf(v0, fmaxf(v1, v2));
    #pragma unroll
    for (int off = 16; off >= 1; off >>= 1) m = fmaxf(m, __shfl_xor_sync(0xFFFFFFFFu, m, off));
    float s = expf(v0 - m) + expf(v1 - m) + expf(v2 - m);
    #pragma unroll
    for (int off = 16; off >= 1; off >>= 1) s += __shfl_xor_sync(0xFFFFFFFFu, s, off);
    if (lane == 0) g_nll[gw] = m + logf(s) - L[lab];
}

__global__ void ce2_kernel(float* __restrict__ out) {
    int t = threadIdx.x;
    float v = (t < 2 * BB) ? g_nll[t] : 0.0f;
    #pragma unroll
    for (int off = 16; off >= 1; off >>= 1) v += __shfl_xor_sync(0xFFFFFFFFu, v, off);
    __shared__ float sh[8];
    if ((t & 31) == 0) sh[t >> 5] = v;
    __syncthreads();
    if (t == 0) {
        float s = 0.0f;
        #pragma unroll
        for (int ww = 0; ww < 8; ww++) s += sh[ww];
        out[0] = s * (1.0f / (2.0f * BB));
    }
}

extern "C" void kernel_launch(void* const* d_in, const int* in_sizes, int n_in,
                              void* d_out, int out_size) {
    const float* img = (const float*)d_in[0];
    const float* txt = (const float*)d_in[1];
    float* out = (float*)d_out;
    (void)in_sizes; (void)n_in; (void)out_size;

    cudaFuncSetAttribute(sim_kernel, cudaFuncAttributeMaxDynamicSharedMemorySize, SMEM_BYTES);

    long long total = (long long)BB * NQ * DIMK + (long long)BB * NR * DIMK;
    prep_kernel<<<(unsigned)((total + 255) / 256), 256>>>(img, txt);

    dim3 grid(BB, BB);
    sim_kernel<<<grid, NTHREAD, SMEM_BYTES>>>();

    ce1_kernel<<<(2 * BB * 32) / 256, 256>>>();
    ce2_kernel<<<1, 256>>>(out);
}

// round 14
// speedup vs baseline: 6.5760x; 1.3318x over previous
#include <cuda_runtime.h>
#include <cuda_fp16.h>
#include <cstdint>
#include <math.h>

#define BB   96
#define NQ   196
#define NR   77
#define DIMK 512
#define KC   64            // k per chunk
#define NCHUNK (DIMK / KC) // 8
#define MT   13            // m16 tiles (208 rows)
#define NT   10            // n8 tiles (80 cols)
#define NWARP 26           // warp = (c, mt), c in {0,1}
#define NTHREAD (NWARP * 32)   // 832
#define NSTAGE 3

// ---- smem layout. Row stride 144B (9x16B, conflict-free ldmatrix). ----
#define RB       144
#define A_SZ     (208 * RB)       // 29952
#define B1_SZ    (80 * RB)        // 11520 (one c)
#define OFF_A    0
#define OFF_B    (OFF_A + A_SZ)   // two c's back to back
#define STAGE_SZ (OFF_B + 2 * B1_SZ)   // 52992
#define SMEM_BYTES (NSTAGE * STAGE_SZ) // 158976
// epilogue scratch reuses stage0 (safe: stage0's last producer is chunk 6,
// fenced from every warp by the ck=7 top-of-loop __syncthreads)
#define EP_ROW   0                 // 2 x 208 floats
#define EP_COL   2048              // 2 x 13 x 80 floats

__device__ __forceinline__ uint32_t smem_u32(const void* p) {
    uint32_t a;
    asm("{ .reg .u64 t; cvta.to.shared.u64 t, %1; cvt.u32.u64 %0, t; }" : "=r"(a) : "l"(p));
    return a;
}

#define CP_ASYNC16(d, s) asm volatile("cp.async.cg.shared.global [%0], [%1], 16;" :: "r"(d), "l"(s) : "memory")
#define CP_COMMIT()      asm volatile("cp.async.commit_group;" ::: "memory")
#define CP_WAIT1()       asm volatile("cp.async.wait_group 1;" ::: "memory")
#define CP_WAIT0()       asm volatile("cp.async.wait_group 0;" ::: "memory")

#define LDSM_X4(r0, r1, r2, r3, a) \
    asm volatile("ldmatrix.sync.aligned.m8n8.x4.shared.b16 {%0,%1,%2,%3}, [%4];" \
        : "=r"(r0), "=r"(r1), "=r"(r2), "=r"(r3) : "r"(a))

#define MMA_F16(d, a, b0, b1) \
    asm volatile("mma.sync.aligned.m16n8k16.row.col.f32.f16.f16.f32 " \
        "{%0,%1,%2,%3},{%4,%5,%6,%7},{%8,%9},{%0,%1,%2,%3};" \
        : "+f"((d)[0]), "+f"((d)[1]), "+f"((d)[2]), "+f"((d)[3]) \
        : "r"((a)[0]), "r"((a)[1]), "r"((a)[2]), "r"((a)[3]), "r"(b0), "r"(b1))

// ---------------- global scratch ----------------
__device__ __half g_img[BB * NQ * DIMK];
__device__ __half g_txt[BB * NR * DIMK];
__device__ float g_i2t[BB * BB];
__device__ float g_t2i[BB * BB];
__device__ float g_nll[2 * BB];

// ---------------- prep: fp32 -> fp16 ----------------
__global__ void prep_kernel(const float* __restrict__ img, const float* __restrict__ txt) {
    const long long TI = (long long)BB * NQ * DIMK;
    const long long TT = (long long)BB * NR * DIMK;
    long long i = (long long)blockIdx.x * blockDim.x + threadIdx.x;
    if (i < TI) {
        g_img[i] = __float2half(img[i]);
    } else if (i < TI + TT) {
        long long j = i - TI;
        g_txt[j] = __float2half(txt[j]);
    }
}

// ---------------- chunk loader: A once, B for both c's ----------------
__device__ __forceinline__ void load_chunk(uint32_t smb, uint32_t stage_off,
                                           int b, int c0, int k0, int tid) {
    // A: 196 rows x 8 segs of 16B (shared by both c groups)
    for (int idx = tid; idx < NQ * 8; idx += NTHREAD) {
        int q = idx >> 3, seg = idx & 7;
        const char* src = (const char*)(g_img + (size_t)(b * NQ + q) * DIMK + k0) + seg * 16;
        uint32_t dst = smb + stage_off + OFF_A + q * RB + seg * 16;
        CP_ASYNC16(dst, src);
    }
    // B: 2 c's x 77 rows x 8 segs
    for (int idx = tid; idx < 2 * NR * 8; idx += NTHREAD) {
        int cc = idx / (NR * 8), rem = idx % (NR * 8);
        int n = rem >> 3, seg = rem & 7;
        const char* src = (const char*)(g_txt + (size_t)((c0 + cc) * NR + n) * DIMK + k0) + seg * 16;
        uint32_t dst = smb + stage_off + OFF_B + cc * B1_SZ + n * RB + seg * 16;
        CP_ASYNC16(dst, src);
    }
}

// ---------------- main MMA kernel: one CTA per (b, c-pair) ----------------
__global__ __launch_bounds__(NTHREAD, 1) void sim_kernel() {
    extern __shared__ __align__(128) char smp[];
    const uint32_t smb = smem_u32(smp);
    const int tid = threadIdx.x;
    const int w = tid >> 5, lane = tid & 31;
    const int cg = w / MT;        // 0 or 1: which c of the pair
    const int mt = w % MT;        // m-tile
    const int b = blockIdx.x, c0 = blockIdx.y * 2;

    // zero pad rows (A rows 196..207; B rows 77..79 x 2 c; all stages; 36 words/row)
    for (int idx = tid; idx < NSTAGE * 12 * 36; idx += NTHREAD) {
        int s = idx / (12 * 36), rem = idx % (12 * 36);
        int row = 196 + rem / 36, word = rem % 36;
        *(uint32_t*)(smp + s * STAGE_SZ + OFF_A + row * RB + word * 4) = 0;
    }
    for (int idx = tid; idx < NSTAGE * 2 * 3 * 36; idx += NTHREAD) {
        int s = idx / (2 * 3 * 36), rem = idx % (2 * 3 * 36);
        int cc = rem / (3 * 36); rem %= 3 * 36;
        int row = 77 + rem / 36, word = rem % 36;
        *(uint32_t*)(smp + s * STAGE_SZ + OFF_B + cc * B1_SZ + row * RB + word * 4) = 0;
    }

    // ldmatrix per-lane address offsets (within a stage)
    const int j = lane >> 3, r8 = lane & 7;
    const uint32_t aoff  = (uint32_t)((mt * 16 + r8 + (j & 1) * 8) * RB + (j >> 1) * 16);
    const uint32_t boff0 = (uint32_t)(cg * B1_SZ + ((j >> 1) * 8 + r8) * RB + (j & 1) * 16);

    float acc[NT * 4];
    #pragma unroll
    for (int i = 0; i < NT * 4; i++) acc[i] = 0.0f;

    // prologue: 2 chunks in flight
    load_chunk(smb, 0 * STAGE_SZ, b, c0, 0, tid);
    CP_COMMIT();
    load_chunk(smb, 1 * STAGE_SZ, b, c0, KC, tid);
    CP_COMMIT();

    for (int ck = 0; ck < NCHUNK; ck++) {
        if (ck < NCHUNK - 1) CP_WAIT1();   // chunk ck landed (ck+1 may be pending)
        else                 CP_WAIT0();
        __syncthreads();                   // also fences compute(ck-1) on all warps
        if (ck + 2 < NCHUNK) {
            load_chunk(smb, (uint32_t)((ck + 2) % NSTAGE) * STAGE_SZ, b, c0, (ck + 2) * KC, tid);
            CP_COMMIT();
        }

        const uint32_t st = smb + (uint32_t)(ck % NSTAGE) * STAGE_SZ;
        #pragma unroll
        for (int ks = 0; ks < 4; ks++) {
            const uint32_t kb = ks * 32;
            uint32_t ah[4], b0[4], b1[4];
            LDSM_X4(ah[0], ah[1], ah[2], ah[3], st + OFF_A + aoff + kb);
            LDSM_X4(b0[0], b0[1], b0[2], b0[3], st + OFF_B + boff0 + kb);
            #pragma unroll
            for (int p = 0; p < 5; p++) {
                uint32_t* cur = (p & 1) ? b1 : b0;
                uint32_t* nxt = (p & 1) ? b0 : b1;
                if (p < 4) {
                    LDSM_X4(nxt[0], nxt[1], nxt[2], nxt[3],
                            st + OFF_B + boff0 + (uint32_t)((p + 1) * 16 * RB) + kb);
                }
                MMA_F16(acc + (2 * p) * 4,     ah, cur[0], cur[1]);
                MMA_F16(acc + (2 * p + 1) * 4, ah, cur[2], cur[3]);
            }
        }
    }

    // -------- epilogue (stage0 reuse: safe, see header note) --------
    float* rowRes  = (float*)(smp + EP_ROW);   // [2][208]
    float* colPart = (float*)(smp + EP_COL);   // [2][13][80]
    const int r0 = mt * 16 + (lane >> 2);
    const int r1 = r0 + 8;

    // rowmax (mask pad cols >= 77)
    float rm0 = -INFINITY, rm1 = -INFINITY;
    #pragma unroll
    for (int n = 0; n < NT; n++) {
        #pragma unroll
        for (int e = 0; e < 2; e++) {
            int col = n * 8 + ((lane & 3) << 1) + e;
            if (col < NR) {
                rm0 = fmaxf(rm0, acc[n * 4 + e]);
                rm1 = fmaxf(rm1, acc[n * 4 + 2 + e]);
            }
        }
    }
    rm0 = fmaxf(rm0, __shfl_xor_sync(0xFFFFFFFFu, rm0, 1));
    rm0 = fmaxf(rm0, __shfl_xor_sync(0xFFFFFFFFu, rm0, 2));
    rm1 = fmaxf(rm1, __shfl_xor_sync(0xFFFFFFFFu, rm1, 1));
    rm1 = fmaxf(rm1, __shfl_xor_sync(0xFFFFFFFFu, rm1, 2));
    if ((lane & 3) == 0) {
        if (r0 < NQ) rowRes[cg * 208 + r0] = rm0;
        if (r1 < NQ) rowRes[cg * 208 + r1] = rm1;
    }

    // colmax (mask pad rows >= 196)
    #pragma unroll
    for (int n = 0; n < NT; n++) {
        #pragma unroll
        for (int e = 0; e < 2; e++) {
            float v = -INFINITY;
            if (r0 < NQ) v = acc[n * 4 + e];
            if (r1 < NQ) v = fmaxf(v, acc[n * 4 + 2 + e]);
            v = fmaxf(v, __shfl_xor_sync(0xFFFFFFFFu, v, 4));
            v = fmaxf(v, __shfl_xor_sync(0xFFFFFFFFu, v, 8));
            v = fmaxf(v, __shfl_xor_sync(0xFFFFFFFFu, v, 16));
            if (lane < 4) colPart[(cg * MT + mt) * 80 + n * 8 + lane * 2 + e] = v;
        }
    }
    __syncthreads();

    if (mt == 0) {  // i2t: mean of rowmax (warp 0 -> c0, warp 13 -> c1)
        float s = 0.0f;
        for (int q = lane; q < NQ; q += 32) s += rowRes[cg * 208 + q];
        #pragma unroll
        for (int off = 16; off >= 1; off >>= 1) s += __shfl_xor_sync(0xFFFFFFFFu, s, off);
        if (lane == 0) g_i2t[b * BB + c0 + cg] = s * (1.0f / NQ);
    }
    if (mt == 1) {  // t2i: mean of colmax (warp 1 -> c0, warp 14 -> c1)
        float s = 0.0f;
        for (int col = lane; col < NR; col += 32) {
            float m = colPart[(cg * MT) * 80 + col];
            #pragma unroll
            for (int ww = 1; ww < MT; ww++)
                m = fmaxf(m, colPart[(cg * MT + ww) * 80 + col]);
            s += m;
        }
        #pragma unroll
        for (int off = 16; off >= 1; off >>= 1) s += __shfl_xor_sync(0xFFFFFFFFu, s, off);
        if (lane == 0) g_t2i[(c0 + cg) * BB + b] = s * (1.0f / NR);
    }
}

// ---------------- CE: one warp per logit row ----------------
__global__ void ce1_kernel() {
    int gw = (blockIdx.x * blockDim.x + threadIdx.x) >> 5;  // 0..191
    int lane = threadIdx.x & 31;
    const float* L = (gw < BB) ? (g_i2t + gw * BB) : (g_t2i + (gw - BB) * BB);
    int lab = (gw < BB) ? gw : gw - BB;
    float v0 = L[lane], v1 = L[lane + 32], v2 = L[lane + 64];
    float m = fmaxf(v0, fmaxf(v1, v2));
    #pragma unroll
    for (int off = 16; off >= 1; off >>= 1) m = fmaxf(m, __shfl_xor_sync(0xFFFFFFFFu, m, off));
    float s = expf(v0 - m) + expf(v1 - m) + expf(v2 - m);
    #pragma unroll
    for (int off = 16; off >= 1; off >>= 1) s += __shfl_xor_sync(0xFFFFFFFFu, s, off);
    if (lane == 0) g_nll[gw] = m + logf(s) - L[lab];
}

__global__ void ce2_kernel(float* __restrict__ out) {
    int t = threadIdx.x;
    float v = (t < 2 * BB) ? g_nll[t] : 0.0f;
    #pragma unroll
    for (int off = 16; off >= 1; off >>= 1) v += __shfl_xor_sync(0xFFFFFFFFu, v, off);
    __shared__ float sh[8];
    if ((t & 31) == 0) sh[t >> 5] = v;
    __syncthreads();
    if (t == 0) {
        float s = 0.0f;
        #pragma unroll
        for (int ww = 0; ww < 8; ww++) s += sh[ww];
        out[0] = s * (1.0f / (2.0f * BB));
    }
}

extern "C" void kernel_launch(void* const* d_in, const int* in_sizes, int n_in,
                              void* d_out, int out_size) {
    const float* img = (const float*)d_in[0];
    const float* txt = (const float*)d_in[1];
    float* out = (float*)d_out;
    (void)in_sizes; (void)n_in; (void)out_size;

    cudaFuncSetAttribute(sim_kernel, cudaFuncAttributeMaxDynamicSharedMemorySize, SMEM_BYTES);

    long long total = (long long)BB * NQ * DIMK + (long long)BB * NR * DIMK;
    prep_kernel<<<(unsigned)((total + 255) / 256), 256>>>(img, txt);

    dim3 grid(BB, BB / 2);
    sim_kernel<<<grid, NTHREAD, SMEM_BYTES>>>();

    ce1_kernel<<<(2 * BB * 32) / 256, 256>>>();
    ce2_kernel<<<1, 256>>>(out);
}

// round 15
// speedup vs baseline: 7.8606x; 1.1953x over previous
#include <cuda_runtime.h>
#include <cuda_fp16.h>
#include <cstdint>
#include <math.h>

#define BB   96
#define NQ   196
#define NR   77
#define DIMK 512
#define KC   64            // k per chunk
#define NCHUNK (DIMK / KC) // 8
#define MT   13            // m16 tiles (208 rows)
#define NT   10            // n8 tiles (80 cols)
#define NWARP 26           // warp = (cg, mt), cg in {0,1}
#define NTHREAD (NWARP * 32)   // 832
#define NSTAGE 3

// ---- gmem staged tiles (pre-swizzled SW128, chunk-contiguous) ----
#define A_TILE_CP 25088        // 196 rows x 128B
#define B_TILE_CP 9856         // 77 rows x 128B
#define TX_BYTES  (A_TILE_CP + 2 * B_TILE_CP)   // 44800

// ---- smem layout ----
#define OFF_A    0             // 208 rows alloc (196 filled)
#define OFF_B0   26624         // 80 rows alloc (77 filled)
#define OFF_B1   36864
#define STAGE_SZ 47104         // 46 x 1024 (keeps stage bases 1024-aligned)
#define MB_OFF   (NSTAGE * STAGE_SZ)            // 141312: 3 mbarriers
#define SMEM_BYTES (MB_OFF + 64)
// epilogue scratch reuses stage0 (all compute on stage0 data done before epilogue)
#define EP_ROW   0                 // 2 x 208 floats
#define EP_COL   2048              // 2 x 13 x 80 floats

__device__ __forceinline__ uint32_t smem_u32(const void* p) {
    uint32_t a;
    asm("{ .reg .u64 t; cvta.to.shared.u64 t, %1; cvt.u32.u64 %0, t; }" : "=r"(a) : "l"(p));
    return a;
}

#define MBAR_INIT(mb, c) asm volatile("mbarrier.init.shared.b64 [%0], %1;" :: "r"(mb), "r"(c) : "memory")
#define MBAR_EXPECT(mb, n) asm volatile("mbarrier.arrive.expect_tx.shared.b64 _, [%0], %1;" :: "r"(mb), "r"(n) : "memory")
#define FENCE_ASYNC()    asm volatile("fence.proxy.async.shared::cta;" ::: "memory")
#define CP_BULK(dst, src, sz, mb) \
    asm volatile("cp.async.bulk.shared::cluster.global.mbarrier::complete_tx::bytes [%0], [%1], %2, [%3];" \
        :: "r"(dst), "l"(src), "r"(sz), "r"(mb) : "memory")
#define MBAR_WAIT(mb, ph) do {                                                       \
    uint32_t _m = (mb), _p = (ph), _d;                                               \
    asm volatile("{ .reg .pred p; mbarrier.try_wait.parity.acquire.cta.shared::cta.b64 p, [%1], %2; selp.b32 %0,1,0,p; }" \
        : "=r"(_d) : "r"(_m), "r"(_p) : "memory");                                   \
    if (!_d) {                                                                       \
        asm volatile("{ .reg .pred P1; WL_%=: mbarrier.try_wait.parity.acquire.cta.shared::cta.b64 P1, [%0], %1, 0x989680; @P1 bra.uni WD_%=; bra.uni WL_%=; WD_%=: }" \
            :: "r"(_m), "r"(_p) : "memory");                                         \
    } } while (0)

#define LDSM_X4(r0, r1, r2, r3, a) \
    asm volatile("ldmatrix.sync.aligned.m8n8.x4.shared.b16 {%0,%1,%2,%3}, [%4];" \
        : "=r"(r0), "=r"(r1), "=r"(r2), "=r"(r3) : "r"(a))

#define MMA_F16(d, a, b0, b1) \
    asm volatile("mma.sync.aligned.m16n8k16.row.col.f32.f16.f16.f32 " \
        "{%0,%1,%2,%3},{%4,%5,%6,%7},{%8,%9},{%0,%1,%2,%3};" \
        : "+f"((d)[0]), "+f"((d)[1]), "+f"((d)[2]), "+f"((d)[3]) \
        : "r"((a)[0]), "r"((a)[1]), "r"((a)[2]), "r"((a)[3]), "r"(b0), "r"(b1))

// ---------------- global scratch (uint4 => 16B aligned) ----------------
__device__ uint4 g_imgS[BB * NCHUNK * 196 * 8];   // [b][ck][q][seg^q&7], fp16, SW128-swizzled
__device__ uint4 g_txtS[BB * NCHUNK * 77 * 8];    // [c][ck][n][seg^n&7]
__device__ float g_i2t[BB * BB];
__device__ float g_t2i[BB * BB];
__device__ float g_nll[2 * BB];

// ---------------- prep: fp32 -> fp16, chunk-major, pre-swizzled ----------------
__global__ void prep_kernel(const float* __restrict__ img, const float* __restrict__ txt) {
    const int TA = BB * NCHUNK * 196 * 8;   // 1204224
    const int TB = BB * NCHUNK * 77 * 8;    // 473088
    int idx = blockIdx.x * blockDim.x + threadIdx.x;
    const float* src;
    uint4* dst;
    if (idx < TA) {
        int bc = idx / 1568, rem = idx % 1568;        // bc = b*8+ck
        int q = rem >> 3, seg = rem & 7;
        src = img + ((size_t)(bc >> 3) * NQ + q) * DIMK + (bc & 7) * KC + seg * 8;
        dst = g_imgS + (size_t)bc * 1568 + q * 8 + (seg ^ (q & 7));
    } else if (idx < TA + TB) {
        int j = idx - TA;
        int cc = j / 616, rem = j % 616;              // cc = c*8+ck
        int n = rem >> 3, seg = rem & 7;
        src = txt + ((size_t)(cc >> 3) * NR + n) * DIMK + (cc & 7) * KC + seg * 8;
        dst = g_txtS + (size_t)cc * 616 + n * 8 + (seg ^ (n & 7));
    } else return;
    float4 v0 = *(const float4*)src;
    float4 v1 = *(const float4*)(src + 4);
    __half2 h0 = __floats2half2_rn(v0.x, v0.y);
    __half2 h1 = __floats2half2_rn(v0.z, v0.w);
    __half2 h2 = __floats2half2_rn(v1.x, v1.y);
    __half2 h3 = __floats2half2_rn(v1.z, v1.w);
    uint4 o;
    o.x = *(uint32_t*)&h0; o.y = *(uint32_t*)&h1;
    o.z = *(uint32_t*)&h2; o.w = *(uint32_t*)&h3;
    *dst = o;
}

// ---------------- main MMA kernel: one CTA per (b, c-pair) ----------------
__global__ __launch_bounds__(NTHREAD, 1) void sim_kernel() {
    extern __shared__ __align__(1024) char smp[];
    const uint32_t smb = smem_u32(smp);
    const int tid = threadIdx.x;
    const int w = tid >> 5, lane = tid & 31;
    const int cg = w / MT;        // 0 or 1: which c of the pair
    const int mt = w % MT;        // m-tile
    const int b = blockIdx.x, c0 = blockIdx.y * 2;

    if (tid == 0) {
        MBAR_INIT(smb + MB_OFF + 0, 1);
        MBAR_INIT(smb + MB_OFF + 8, 1);
        MBAR_INIT(smb + MB_OFF + 16, 1);
        FENCE_ASYNC();
    }
    __syncthreads();

    // prologue: chunks 0,1 in flight (issued by one thread; 3 bulk copies each)
    if (tid == 0) {
        #pragma unroll
        for (int ck = 0; ck < 2; ck++) {
            uint32_t st = smb + (uint32_t)ck * STAGE_SZ;
            uint32_t mb = smb + MB_OFF + ck * 8;
            MBAR_EXPECT(mb, TX_BYTES);
            CP_BULK(st + OFF_A, (const char*)g_imgS + ((size_t)b * NCHUNK + ck) * A_TILE_CP,
                    A_TILE_CP, mb);
            CP_BULK(st + OFF_B0, (const char*)g_txtS + ((size_t)c0 * NCHUNK + ck) * B_TILE_CP,
                    B_TILE_CP, mb);
            CP_BULK(st + OFF_B1, (const char*)g_txtS + ((size_t)(c0 + 1) * NCHUNK + ck) * B_TILE_CP,
                    B_TILE_CP, mb);
        }
    }

    // per-lane fragment addressing (SW128: xor term r8*16 is lane-constant)
    const int j = lane >> 3, r8 = lane & 7;
    const uint32_t xr = (uint32_t)(r8 * 16);
    const uint32_t aRow = (uint32_t)((mt * 16 + r8 + (j & 1) * 8) * 128);          // + OFF_A
    const uint32_t bRow = (uint32_t)(((j >> 1) * 8 + r8) * 128)
                        + (cg ? OFF_B1 : OFF_B0);
    const uint32_t aCol0 = (uint32_t)((j >> 1) * 16);
    const uint32_t bCol0 = (uint32_t)((j & 1) * 16);

    float acc[NT * 4];
    #pragma unroll
    for (int i = 0; i < NT * 4; i++) acc[i] = 0.0f;

    for (int ck = 0; ck < NCHUNK; ck++) {
        MBAR_WAIT(smb + MB_OFF + (ck % NSTAGE) * 8, (uint32_t)((ck / NSTAGE) & 1));
        __syncthreads();   // all warps done with compute(ck-1) => stage (ck+2)%3 is free
        if (tid == 0 && ck + 2 < NCHUNK) {
            int cn = ck + 2;
            uint32_t st = smb + (uint32_t)(cn % NSTAGE) * STAGE_SZ;
            uint32_t mb = smb + MB_OFF + (cn % NSTAGE) * 8;
            MBAR_EXPECT(mb, TX_BYTES);
            CP_BULK(st + OFF_A, (const char*)g_imgS + ((size_t)b * NCHUNK + cn) * A_TILE_CP,
                    A_TILE_CP, mb);
            CP_BULK(st + OFF_B0, (const char*)g_txtS + ((size_t)c0 * NCHUNK + cn) * B_TILE_CP,
                    B_TILE_CP, mb);
            CP_BULK(st + OFF_B1, (const char*)g_txtS + ((size_t)(c0 + 1) * NCHUNK + cn) * B_TILE_CP,
                    B_TILE_CP, mb);
        }

        const uint32_t st = smb + (uint32_t)(ck % NSTAGE) * STAGE_SZ;
        #pragma unroll
        for (int ks = 0; ks < 4; ks++) {
            const uint32_t kb = (uint32_t)(ks * 32);
            const uint32_t aAddr = st + OFF_A + aRow + ((aCol0 + kb) ^ xr);
            const uint32_t bBase = st + bRow + ((bCol0 + kb) ^ xr);
            uint32_t ah[4], b0[4], b1[4];
            LDSM_X4(ah[0], ah[1], ah[2], ah[3], aAddr);
            LDSM_X4(b0[0], b0[1], b0[2], b0[3], bBase);
            #pragma unroll
            for (int p = 0; p < 5; p++) {
                uint32_t* cur = (p & 1) ? b1 : b0;
                uint32_t* nxt = (p & 1) ? b0 : b1;
                if (p < 4) {
                    LDSM_X4(nxt[0], nxt[1], nxt[2], nxt[3],
                            bBase + (uint32_t)((p + 1) * 16 * 128));
                }
                MMA_F16(acc + (2 * p) * 4,     ah, cur[0], cur[1]);
                MMA_F16(acc + (2 * p + 1) * 4, ah, cur[2], cur[3]);
            }
        }
    }

    // -------- epilogue (stage0 reuse: all stage0 compute complete) --------
    float* rowRes  = (float*)(smp + EP_ROW);   // [2][208]
    float* colPart = (float*)(smp + EP_COL);   // [2][13][80]
    const int r0 = mt * 16 + (lane >> 2);
    const int r1 = r0 + 8;

    // rowmax (mask pad cols >= 77)
    float rm0 = -INFINITY, rm1 = -INFINITY;
    #pragma unroll
    for (int n = 0; n < NT; n++) {
        #pragma unroll
        for (int e = 0; e < 2; e++) {
            int col = n * 8 + ((lane & 3) << 1) + e;
            if (col < NR) {
                rm0 = fmaxf(rm0, acc[n * 4 + e]);
                rm1 = fmaxf(rm1, acc[n * 4 + 2 + e]);
            }
        }
    }
    rm0 = fmaxf(rm0, __shfl_xor_sync(0xFFFFFFFFu, rm0, 1));
    rm0 = fmaxf(rm0, __shfl_xor_sync(0xFFFFFFFFu, rm0, 2));
    rm1 = fmaxf(rm1, __shfl_xor_sync(0xFFFFFFFFu, rm1, 1));
    rm1 = fmaxf(rm1, __shfl_xor_sync(0xFFFFFFFFu, rm1, 2));
    __syncthreads();   // ensure every warp is past its last stage0 LDSM before EP writes
    if ((lane & 3) == 0) {
        if (r0 < NQ) rowRes[cg * 208 + r0] = rm0;
        if (r1 < NQ) rowRes[cg * 208 + r1] = rm1;
    }

    // colmax (mask pad rows >= 196; garbage tail rows never enter v)
    #pragma unroll
    for (int n = 0; n < NT; n++) {
        #pragma unroll
        for (int e = 0; e < 2; e++) {
            float v = -INFINITY;
            if (r0 < NQ) v = acc[n * 4 + e];
            if (r1 < NQ) v = fmaxf(v, acc[n * 4 + 2 + e]);
            v = fmaxf(v, __shfl_xor_sync(0xFFFFFFFFu, v, 4));
            v = fmaxf(v, __shfl_xor_sync(0xFFFFFFFFu, v, 8));
            v = fmaxf(v, __shfl_xor_sync(0xFFFFFFFFu, v, 16));
            if (lane < 4) colPart[(cg * MT + mt) * 80 + n * 8 + lane * 2 + e] = v;
        }
    }
    __syncthreads();

    if (mt == 0) {  // i2t: mean of rowmax (warp 0 -> c0, warp 13 -> c1)
        float s = 0.0f;
        for (int q = lane; q < NQ; q += 32) s += rowRes[cg * 208 + q];
        #pragma unroll
        for (int off = 16; off >= 1; off >>= 1) s += __shfl_xor_sync(0xFFFFFFFFu, s, off);
        if (lane == 0) g_i2t[b * BB + c0 + cg] = s * (1.0f / NQ);
    }
    if (mt == 1) {  // t2i: mean of colmax (warp 1 -> c0, warp 14 -> c1)
        float s = 0.0f;
        for (int col = lane; col < NR; col += 32) {
            float m = colPart[(cg * MT) * 80 + col];
            #pragma unroll
            for (int ww = 1; ww < MT; ww++)
                m = fmaxf(m, colPart[(cg * MT + ww) * 80 + col]);
            s += m;
        }
        #pragma unroll
        for (int off = 16; off >= 1; off >>= 1) s += __shfl_xor_sync(0xFFFFFFFFu, s, off);
        if (lane == 0) g_t2i[(c0 + cg) * BB + b] = s * (1.0f / NR);
    }
}

// ---------------- CE: one warp per logit row ----------------
__global__ void ce1_kernel() {
    int gw = (blockIdx.x * blockDim.x + threadIdx.x) >> 5;  // 0..191
    int lane = threadIdx.x & 31;
    const float* L = (gw < BB) ? (g_i2t + gw * BB) : (g_t2i + (gw - BB) * BB);
    int lab = (gw < BB) ? gw : gw - BB;
    float v0 = L[lane], v1 = L[lane + 32], v2 = L[lane + 64];
    float m = fmaxf(v0, fmaxf(v1, v2));
    #pragma unroll
    for (int off = 16; off >= 1; off >>= 1) m = fmaxf(m, __shfl_xor_sync(0xFFFFFFFFu, m, off));
    float s = expf(v0 - m) + expf(v1 - m) + expf(v2 - m);
    #pragma unroll
    for (int off = 16; off >= 1; off >>= 1) s += __shfl_xor_sync(0xFFFFFFFFu, s, off);
    if (lane == 0) g_nll[gw] = m + logf(s) - L[lab];
}

__global__ void ce2_kernel(float* __restrict__ out) {
    int t = threadIdx.x;
    float v = (t < 2 * BB) ? g_nll[t] : 0.0f;
    #pragma unroll
    for (int off = 16; off >= 1; off >>= 1) v += __shfl_xor_sync(0xFFFFFFFFu, v, off);
    __shared__ float sh[8];
    if ((t & 31) == 0) sh[t >> 5] = v;
    __syncthreads();
    if (t == 0) {
        float s = 0.0f;
        #pragma unroll
        for (int ww = 0; ww < 8; ww++) s += sh[ww];
        out[0] = s * (1.0f / (2.0f * BB));
    }
}

extern "C" void kernel_launch(void* const* d_in, const int* in_sizes, int n_in,
                              void* d_out, int out_size) {
    const float* img = (const float*)d_in[0];
    const float* txt = (const float*)d_in[1];
    float* out = (float*)d_out;
    (void)in_sizes; (void)n_in; (void)out_size;

    cudaFuncSetAttribute(sim_kernel, cudaFuncAttributeMaxDynamicSharedMemorySize, SMEM_BYTES);

    int total = BB * NCHUNK * 196 * 8 + BB * NCHUNK * 77 * 8;
    prep_kernel<<<(total + 255) / 256, 256>>>(img, txt);

    dim3 grid(BB, BB / 2);
    sim_kernel<<<grid, NTHREAD, SMEM_BYTES>>>();

    ce1_kernel<<<(2 * BB * 32) / 256, 256>>>();
    ce2_kernel<<<1, 256>>>(out);
}